// round 1
// baseline (speedup 1.0000x reference)
#include <cuda_runtime.h>
#include <math.h>

// Problem constants
#define NTOK 4096
#define DDIM 1024
#define HDIM 2048
#define NEXP 8
#define TOPK 2

// GEMM tiling
#define BM 128
#define BN 128
#define BK 16
#define TM 8
#define TN 8
#define NTHREADS 256

// Scratch (device globals -- no allocation allowed)
__device__ float g_H[(size_t)NTOK * TOPK * HDIM];   // 64 MB: relu(x@W1+b1) per slot
__device__ float g_Y[(size_t)NTOK * TOPK * DDIM];   // 32 MB: h@W2+b2 per slot
__device__ float g_gate[NTOK * TOPK];               // gate prob per slot
__device__ int   g_counts[NEXP];                    // tokens routed per expert
__device__ int   g_slots[NEXP][NTOK];               // slot-id (n*2+k) list per expert

// ---------------------------------------------------------------------------
__global__ void zero_counts_kernel() {
    if (threadIdx.x < NEXP) g_counts[threadIdx.x] = 0;
}

// ---------------------------------------------------------------------------
// Gating: one warp per token. logits = x@gate_W + gate_b; softmax; top-2.
__global__ void gate_kernel(const float* __restrict__ x,
                            const float* __restrict__ gW,
                            const float* __restrict__ gb) {
    int tok  = (blockIdx.x * blockDim.x + threadIdx.x) >> 5;
    int lane = threadIdx.x & 31;
    if (tok >= NTOK) return;

    const float* xr = x + (size_t)tok * DDIM;
    float acc[NEXP];
#pragma unroll
    for (int e = 0; e < NEXP; e++) acc[e] = 0.f;

    for (int j = lane; j < DDIM; j += 32) {
        float xv = xr[j];
        const float4* w4 = (const float4*)(gW + (size_t)j * NEXP);
        float4 w0 = w4[0], w1 = w4[1];
        acc[0] += xv * w0.x; acc[1] += xv * w0.y;
        acc[2] += xv * w0.z; acc[3] += xv * w0.w;
        acc[4] += xv * w1.x; acc[5] += xv * w1.y;
        acc[6] += xv * w1.z; acc[7] += xv * w1.w;
    }
#pragma unroll
    for (int e = 0; e < NEXP; e++) {
#pragma unroll
        for (int o = 16; o > 0; o >>= 1)
            acc[e] += __shfl_xor_sync(0xffffffffu, acc[e], o);
    }

    if (lane == 0) {
        float p[NEXP];
        float mx = -1e30f;
#pragma unroll
        for (int e = 0; e < NEXP; e++) {
            p[e] = acc[e] + gb[e];
            mx = fmaxf(mx, p[e]);
        }
        float s = 0.f;
#pragma unroll
        for (int e = 0; e < NEXP; e++) { p[e] = expf(p[e] - mx); s += p[e]; }
        float inv = 1.f / s;

        // top-2 (stable: strict > keeps lowest index on ties, like lax.top_k)
        int i0 = 0;
#pragma unroll
        for (int e = 1; e < NEXP; e++) if (p[e] > p[i0]) i0 = e;
        int i1 = (i0 == 0) ? 1 : 0;
#pragma unroll
        for (int e = 0; e < NEXP; e++)
            if (e != i0 && p[e] > p[i1]) i1 = e;

        int s0 = atomicAdd(&g_counts[i0], 1);
        g_slots[i0][s0]    = tok * 2;
        g_gate[tok * 2]     = p[i0] * inv;
        int s1 = atomicAdd(&g_counts[i1], 1);
        g_slots[i1][s1]    = tok * 2 + 1;
        g_gate[tok * 2 + 1] = p[i1] * inv;
    }
}

// ---------------------------------------------------------------------------
// Grouped GEMM. FIRST: A = gathered x rows (token = sid>>1), out = relu(.+b1)->g_H.
// !FIRST: A = g_H rows (by sid),  out = .+b2 -> g_Y.
// grid = (NDIM/BN, ceil(maxM/BM), NEXP); blocks past g_counts[e] exit early.
template<int KDIM, int NDIM, bool FIRST>
__global__ __launch_bounds__(NTHREADS)
void moe_gemm_kernel(const float* __restrict__ x,
                     const float* __restrict__ W,
                     const float* __restrict__ bias) {
    const int e   = blockIdx.z;
    const int cnt = g_counts[e];
    const int m0  = blockIdx.y * BM;
    if (m0 >= cnt) return;
    const int n0  = blockIdx.x * BN;

    const float* __restrict__ Asrc = FIRST ? x : g_H;
    float* __restrict__ Out        = FIRST ? g_H : g_Y;
    const float* __restrict__ B    = W + (size_t)e * KDIM * NDIM;

    __shared__ float As[BK][BM + 4];   // A^T, padded
    __shared__ float Bs[BK][BN];
    __shared__ int   s_sid[BM];

    const int tid = threadIdx.x;
    if (tid < BM) {
        int r = m0 + tid;
        s_sid[tid] = (r < cnt) ? g_slots[e][r] : -1;
    }
    __syncthreads();

    // A load mapping: 128 rows x 16 cols; each thread: 1 row, 8 cols (2 float4)
    const int a_row = tid >> 1;
    const int a_col = (tid & 1) * 8;
    int sidA = s_sid[a_row];
    const float* a_ptr = nullptr;
    if (sidA >= 0) {
        size_t row = FIRST ? (size_t)(sidA >> 1) : (size_t)sidA;
        a_ptr = Asrc + row * KDIM;
    }

    // B load mapping: 16 rows x 128 cols; each thread: 2 float4 (rows r, r+8)
    const int b_row = tid >> 5;        // 0..7
    const int b_col = (tid & 31) * 4;  // 0..124

    float acc[TM][TN];
#pragma unroll
    for (int i = 0; i < TM; i++)
#pragma unroll
        for (int j = 0; j < TN; j++) acc[i][j] = 0.f;

    const int tm = (tid >> 4) * TM;    // row base in tile
    const int tn = (tid & 15) * TN;    // col base in tile

    for (int k0 = 0; k0 < KDIM; k0 += BK) {
        float4 av0, av1;
        if (a_ptr) {
            av0 = *(const float4*)(a_ptr + k0 + a_col);
            av1 = *(const float4*)(a_ptr + k0 + a_col + 4);
        } else {
            av0 = make_float4(0.f, 0.f, 0.f, 0.f);
            av1 = av0;
        }
        As[a_col + 0][a_row] = av0.x;
        As[a_col + 1][a_row] = av0.y;
        As[a_col + 2][a_row] = av0.z;
        As[a_col + 3][a_row] = av0.w;
        As[a_col + 4][a_row] = av1.x;
        As[a_col + 5][a_row] = av1.y;
        As[a_col + 6][a_row] = av1.z;
        As[a_col + 7][a_row] = av1.w;

        *(float4*)&Bs[b_row][b_col] =
            *(const float4*)(B + (size_t)(k0 + b_row) * NDIM + n0 + b_col);
        *(float4*)&Bs[b_row + 8][b_col] =
            *(const float4*)(B + (size_t)(k0 + b_row + 8) * NDIM + n0 + b_col);
        __syncthreads();

#pragma unroll
        for (int kk = 0; kk < BK; kk++) {
            float af[TM], bf[TN];
            float4 a0 = *(const float4*)&As[kk][tm];
            float4 a1 = *(const float4*)&As[kk][tm + 4];
            af[0] = a0.x; af[1] = a0.y; af[2] = a0.z; af[3] = a0.w;
            af[4] = a1.x; af[5] = a1.y; af[6] = a1.z; af[7] = a1.w;
            float4 b0 = *(const float4*)&Bs[kk][tn];
            float4 b1 = *(const float4*)&Bs[kk][tn + 4];
            bf[0] = b0.x; bf[1] = b0.y; bf[2] = b0.z; bf[3] = b0.w;
            bf[4] = b1.x; bf[5] = b1.y; bf[6] = b1.z; bf[7] = b1.w;
#pragma unroll
            for (int i = 0; i < TM; i++)
#pragma unroll
                for (int j = 0; j < TN; j++)
                    acc[i][j] += af[i] * bf[j];
        }
        __syncthreads();
    }

    // Epilogue: + bias, optional relu, vectorized store to slot-indexed rows.
    float bv[TN];
    const float* brow = bias + (size_t)e * NDIM + n0 + tn;
#pragma unroll
    for (int j = 0; j < TN; j++) bv[j] = brow[j];

#pragma unroll
    for (int i = 0; i < TM; i++) {
        int sid = s_sid[tm + i];
        if (sid < 0) continue;
        float* orow = Out + (size_t)sid * NDIM + n0 + tn;
        float v[TN];
#pragma unroll
        for (int j = 0; j < TN; j++) {
            float t = acc[i][j] + bv[j];
            if (FIRST) t = fmaxf(t, 0.f);
            v[j] = t;
        }
        *(float4*)(orow)     = make_float4(v[0], v[1], v[2], v[3]);
        *(float4*)(orow + 4) = make_float4(v[4], v[5], v[6], v[7]);
    }
}

// ---------------------------------------------------------------------------
// out[n] = gate0 * Y[2n] + gate1 * Y[2n+1]
__global__ void combine_kernel(float* __restrict__ out) {
    int idx = blockIdx.x * blockDim.x + threadIdx.x;
    const int nd4 = DDIM / 4;
    int n = idx / nd4;
    int c = idx % nd4;
    if (n >= NTOK) return;
    float g0 = g_gate[2 * n];
    float g1 = g_gate[2 * n + 1];
    float4 a = ((const float4*)(g_Y + (size_t)(2 * n) * DDIM))[c];
    float4 b = ((const float4*)(g_Y + (size_t)(2 * n + 1) * DDIM))[c];
    float4 r;
    r.x = g0 * a.x + g1 * b.x;
    r.y = g0 * a.y + g1 * b.y;
    r.z = g0 * a.z + g1 * b.z;
    r.w = g0 * a.w + g1 * b.w;
    ((float4*)out)[idx] = r;
}

// ---------------------------------------------------------------------------
extern "C" void kernel_launch(void* const* d_in, const int* in_sizes, int n_in,
                              void* d_out, int out_size) {
    const float* x  = (const float*)d_in[0];
    const float* gW = (const float*)d_in[1];
    const float* gb = (const float*)d_in[2];
    const float* W1 = (const float*)d_in[3];
    const float* b1 = (const float*)d_in[4];
    const float* W2 = (const float*)d_in[5];
    const float* b2 = (const float*)d_in[6];
    float* out = (float*)d_out;
    (void)in_sizes; (void)n_in; (void)out_size;

    zero_counts_kernel<<<1, 32>>>();
    gate_kernel<<<NTOK / 8, 256>>>(x, gW, gb);

    dim3 grid1(HDIM / BN, NTOK / BM, NEXP);   // (16, 32, 8)
    moe_gemm_kernel<DDIM, HDIM, true><<<grid1, NTHREADS>>>(x, W1, b1);

    dim3 grid2(DDIM / BN, NTOK / BM, NEXP);   // (8, 32, 8)
    moe_gemm_kernel<HDIM, DDIM, false><<<grid2, NTHREADS>>>(x, W2, b2);

    combine_kernel<<<(NTOK * (DDIM / 4)) / 256, 256>>>(out);
}

// round 12
// speedup vs baseline: 2.1571x; 2.1571x over previous
#include <cuda_runtime.h>
#include <cuda_bf16.h>
#include <cstdint>
#include <math.h>

// ---------------------------------------------------------------- constants
#define NTOK 4096
#define DDIM 1024
#define HDIM 2048
#define NEXP 8
#define NSLOT (NTOK * 2)

#define BM 128
#define BN 128
#define BK 16                  // bf16 elements per K-stage (one m16n8k16 step)
#define GEMM_THREADS 256
#define ROW_B 80               // 32 data bytes + pad; word-stride 20 -> conflict-free frags
#define TILE_B (BM * ROW_B)    // 10240 B per tile
// 4 tiles (Ahi, Alo, Bhi, Blo), single buffer: 40960 B static shared

// ---------------------------------------------------------------- scratch
__device__ float g_H[(size_t)NSLOT * HDIM];   // 64 MB fp32 hidden
__device__ float g_Y[(size_t)NSLOT * DDIM];   // 32 MB fp32 expert outputs
__device__ float g_gate[NSLOT];
__device__ int   g_counts[NEXP];
__device__ int   g_slots[NEXP][NTOK];

// ---------------------------------------------------------------- PTX helpers
__device__ __forceinline__ void mma_bf16(float* c, const uint32_t* a, const uint32_t* b) {
    asm volatile(
        "mma.sync.aligned.m16n8k16.row.col.f32.bf16.bf16.f32 "
        "{%0,%1,%2,%3},{%4,%5,%6,%7},{%8,%9},{%0,%1,%2,%3};"
        : "+f"(c[0]), "+f"(c[1]), "+f"(c[2]), "+f"(c[3])
        : "r"(a[0]), "r"(a[1]), "r"(a[2]), "r"(a[3]), "r"(b[0]), "r"(b[1]));
}
__device__ __forceinline__ uint32_t pack_hi2(float v0, float v1) {
    __nv_bfloat16 h0 = __float2bfloat16(v0);
    __nv_bfloat16 h1 = __float2bfloat16(v1);
    return (uint32_t)__bfloat16_as_ushort(h0) |
           ((uint32_t)__bfloat16_as_ushort(h1) << 16);
}
__device__ __forceinline__ uint32_t pack_lo2(float v0, float v1) {
    __nv_bfloat16 h0 = __float2bfloat16(v0);
    __nv_bfloat16 h1 = __float2bfloat16(v1);
    __nv_bfloat16 l0 = __float2bfloat16(v0 - __bfloat162float(h0));
    __nv_bfloat16 l1 = __float2bfloat16(v1 - __bfloat162float(h1));
    return (uint32_t)__bfloat16_as_ushort(l0) |
           ((uint32_t)__bfloat16_as_ushort(l1) << 16);
}

// ---------------------------------------------------------------- small kernels
__global__ void zero_counts_kernel() {
    if (threadIdx.x < NEXP) g_counts[threadIdx.x] = 0;
}

// Gating: one warp per token (validated in R1)
__global__ void gate_kernel(const float* __restrict__ x,
                            const float* __restrict__ gW,
                            const float* __restrict__ gb) {
    int tok  = (blockIdx.x * blockDim.x + threadIdx.x) >> 5;
    int lane = threadIdx.x & 31;
    if (tok >= NTOK) return;
    const float* xr = x + (size_t)tok * DDIM;
    float acc[NEXP];
#pragma unroll
    for (int e = 0; e < NEXP; e++) acc[e] = 0.f;
    for (int j = lane; j < DDIM; j += 32) {
        float xv = xr[j];
        const float4* w4 = (const float4*)(gW + (size_t)j * NEXP);
        float4 w0 = w4[0], w1 = w4[1];
        acc[0] += xv * w0.x; acc[1] += xv * w0.y;
        acc[2] += xv * w0.z; acc[3] += xv * w0.w;
        acc[4] += xv * w1.x; acc[5] += xv * w1.y;
        acc[6] += xv * w1.z; acc[7] += xv * w1.w;
    }
#pragma unroll
    for (int e = 0; e < NEXP; e++)
#pragma unroll
        for (int o = 16; o > 0; o >>= 1)
            acc[e] += __shfl_xor_sync(0xffffffffu, acc[e], o);
    if (lane == 0) {
        float p[NEXP];
        float mx = -1e30f;
#pragma unroll
        for (int e = 0; e < NEXP; e++) { p[e] = acc[e] + gb[e]; mx = fmaxf(mx, p[e]); }
        float s = 0.f;
#pragma unroll
        for (int e = 0; e < NEXP; e++) { p[e] = expf(p[e] - mx); s += p[e]; }
        float inv = 1.f / s;
        int i0 = 0;
#pragma unroll
        for (int e = 1; e < NEXP; e++) if (p[e] > p[i0]) i0 = e;
        int i1 = (i0 == 0) ? 1 : 0;
#pragma unroll
        for (int e = 0; e < NEXP; e++) if (e != i0 && p[e] > p[i1]) i1 = e;
        int s0 = atomicAdd(&g_counts[i0], 1);
        g_slots[i0][s0]     = tok * 2;
        g_gate[tok * 2]     = p[i0] * inv;
        int s1 = atomicAdd(&g_counts[i1], 1);
        g_slots[i1][s1]     = tok * 2 + 1;
        g_gate[tok * 2 + 1] = p[i1] * inv;
    }
}

// ---------------------------------------------------------------- mma.sync grouped GEMM
// C[128,128] = gathered fp32 A rows x W (fp32, native [K][N] layout = B^T).
// bf16 hi/lo split done in registers during the gmem->smem stage.
// 3 mma passes: hi*hi + hi*lo + lo*hi, fp32 accum.
// 8 warps, 2(m) x 4(n), warp tile 64x32. Single smem buffer + ldg prefetch.
template <int KDIM, int NDIM, bool FIRST>
__global__ __launch_bounds__(GEMM_THREADS)
void moe_mma_kernel(const float* __restrict__ x,
                    const float* __restrict__ W,
                    const float* __restrict__ bias) {
    constexpr int NC = KDIM / BK;

    const int e   = blockIdx.z;
    const int cnt = g_counts[e];
    const int m0  = blockIdx.y * BM;
    if (m0 >= cnt) return;
    const int n0  = blockIdx.x * BN;

    __shared__ int s_sid[BM];
    __shared__ __align__(16) char smem[4 * TILE_B];  // Ahi | Alo | Bhi | Blo

    const int tid  = threadIdx.x;
    const int wid  = tid >> 5;
    const int lane = tid & 31;

    if (tid < BM) {
        int r = m0 + tid;
        s_sid[tid] = (r < cnt) ? g_slots[e][r] : -1;
    }
    __syncthreads();

    const float* Asrc = FIRST ? x : g_H;                 // rows of fp32
    const float* Bsrc = W + (size_t)e * KDIM * NDIM;     // [K][N], n contiguous

    // Loader mapping: half = tid&1 (k sub-block of 8), lrw = tid>>1 (row / n)
    const int half = tid & 1;
    const int lrw  = tid >> 1;
    const int l_sid = s_sid[lrw];
    size_t l_arow = 0;
    if (l_sid >= 0) l_arow = FIRST ? (size_t)(l_sid >> 1) : (size_t)l_sid;

    float av[8], bv[8];
    auto ldg_stage = [&](int kc) {
        const int k0 = kc * BK + half * 8;
        if (l_sid >= 0) {
            const float* ap = Asrc + l_arow * KDIM + k0;
            float4 p = *(const float4*)(ap);
            float4 q = *(const float4*)(ap + 4);
            av[0] = p.x; av[1] = p.y; av[2] = p.z; av[3] = p.w;
            av[4] = q.x; av[5] = q.y; av[6] = q.z; av[7] = q.w;
        } else {
#pragma unroll
            for (int j = 0; j < 8; j++) av[j] = 0.f;
        }
#pragma unroll
        for (int kk = 0; kk < 8; kk++)
            bv[kk] = Bsrc[(size_t)(k0 + kk) * NDIM + n0 + lrw];
    };

    auto sts_stage = [&]() {
        const int off = lrw * ROW_B + half * 16;
        char* Ahi = smem;
        char* Alo = smem + TILE_B;
        char* Bhi = smem + 2 * TILE_B;
        char* Blo = smem + 3 * TILE_B;
#pragma unroll
        for (int q = 0; q < 4; q++) {
            *(uint32_t*)(Ahi + off + q * 4) = pack_hi2(av[2 * q], av[2 * q + 1]);
            *(uint32_t*)(Alo + off + q * 4) = pack_lo2(av[2 * q], av[2 * q + 1]);
            *(uint32_t*)(Bhi + off + q * 4) = pack_hi2(bv[2 * q], bv[2 * q + 1]);
            *(uint32_t*)(Blo + off + q * 4) = pack_lo2(bv[2 * q], bv[2 * q + 1]);
        }
    };

    // ---- compute setup ----
    const int m_base = (wid & 1) * 64;
    const int n_base = (wid >> 1) * 32;
    float acc[4][4][4];
#pragma unroll
    for (int i = 0; i < 4; i++)
#pragma unroll
        for (int j = 0; j < 4; j++)
#pragma unroll
            for (int k = 0; k < 4; k++) acc[i][j][k] = 0.f;

    const int lrow = lane >> 2;        // fragment group row
    const int lkb  = (lane & 3) * 4;   // fragment k byte offset

    auto compute_stage = [&]() {
        const char* Ahi = smem;
        const char* Alo = smem + TILE_B;
        const char* Bhi = smem + 2 * TILE_B;
        const char* Blo = smem + 3 * TILE_B;
        uint32_t ahi[4][4], alo[4][4], bhi[4][2], blo[4][2];
#pragma unroll
        for (int mf = 0; mf < 4; mf++) {
            const int ro = (m_base + mf * 16 + lrow) * ROW_B + lkb;
            ahi[mf][0] = *(const uint32_t*)(Ahi + ro);
            ahi[mf][1] = *(const uint32_t*)(Ahi + ro + 8 * ROW_B);
            ahi[mf][2] = *(const uint32_t*)(Ahi + ro + 16);
            ahi[mf][3] = *(const uint32_t*)(Ahi + ro + 8 * ROW_B + 16);
            alo[mf][0] = *(const uint32_t*)(Alo + ro);
            alo[mf][1] = *(const uint32_t*)(Alo + ro + 8 * ROW_B);
            alo[mf][2] = *(const uint32_t*)(Alo + ro + 16);
            alo[mf][3] = *(const uint32_t*)(Alo + ro + 8 * ROW_B + 16);
        }
#pragma unroll
        for (int ng = 0; ng < 4; ng++) {
            const int ro = (n_base + ng * 8 + lrow) * ROW_B + lkb;
            bhi[ng][0] = *(const uint32_t*)(Bhi + ro);
            bhi[ng][1] = *(const uint32_t*)(Bhi + ro + 16);
            blo[ng][0] = *(const uint32_t*)(Blo + ro);
            blo[ng][1] = *(const uint32_t*)(Blo + ro + 16);
        }
#pragma unroll
        for (int mf = 0; mf < 4; mf++)
#pragma unroll
            for (int ng = 0; ng < 4; ng++) {
                mma_bf16(acc[mf][ng], ahi[mf], bhi[ng]);
                mma_bf16(acc[mf][ng], ahi[mf], blo[ng]);
                mma_bf16(acc[mf][ng], alo[mf], bhi[ng]);
            }
    };

    // ---- main loop: single buffer, gmem prefetch overlaps compute ----
    ldg_stage(0);
    for (int kc = 0; kc < NC; kc++) {
        __syncthreads();            // previous compute done reading smem
        sts_stage();
        __syncthreads();
        if (kc + 1 < NC) ldg_stage(kc + 1);
        compute_stage();
    }

    // ---- epilogue: fp32 out (g_H for layer 1, g_Y for layer 2) ----
    float* Out = FIRST ? g_H : g_Y;
    const float* brow = bias + (size_t)e * NDIM + n0;
#pragma unroll
    for (int mf = 0; mf < 4; mf++) {
        int r0   = m_base + mf * 16 + lrow;
        int sidA = s_sid[r0];
        int sidB = s_sid[r0 + 8];
#pragma unroll
        for (int ng = 0; ng < 4; ng++) {
            int col = n_base + ng * 8 + (lane & 3) * 2;
            float bv0 = brow[col], bv1 = brow[col + 1];
            float vA0 = acc[mf][ng][0] + bv0, vA1 = acc[mf][ng][1] + bv1;
            float vB0 = acc[mf][ng][2] + bv0, vB1 = acc[mf][ng][3] + bv1;
            if (FIRST) {
                vA0 = fmaxf(vA0, 0.f); vA1 = fmaxf(vA1, 0.f);
                vB0 = fmaxf(vB0, 0.f); vB1 = fmaxf(vB1, 0.f);
            }
            if (sidA >= 0)
                *(float2*)(Out + (size_t)sidA * NDIM + n0 + col) =
                    make_float2(vA0, vA1);
            if (sidB >= 0)
                *(float2*)(Out + (size_t)sidB * NDIM + n0 + col) =
                    make_float2(vB0, vB1);
        }
    }
}

// ---------------------------------------------------------------- combine (validated in R1)
__global__ void combine_kernel(float* __restrict__ out) {
    int idx = blockIdx.x * blockDim.x + threadIdx.x;
    const int nd4 = DDIM / 4;
    int n = idx / nd4;
    int c = idx % nd4;
    if (n >= NTOK) return;
    float g0 = g_gate[2 * n];
    float g1 = g_gate[2 * n + 1];
    float4 a = ((const float4*)(g_Y + (size_t)(2 * n) * DDIM))[c];
    float4 b = ((const float4*)(g_Y + (size_t)(2 * n + 1) * DDIM))[c];
    float4 r;
    r.x = g0 * a.x + g1 * b.x;
    r.y = g0 * a.y + g1 * b.y;
    r.z = g0 * a.z + g1 * b.z;
    r.w = g0 * a.w + g1 * b.w;
    ((float4*)out)[idx] = r;
}

// ---------------------------------------------------------------- launch
extern "C" void kernel_launch(void* const* d_in, const int* in_sizes, int n_in,
                              void* d_out, int out_size) {
    const float* x  = (const float*)d_in[0];
    const float* gW = (const float*)d_in[1];
    const float* gb = (const float*)d_in[2];
    const float* W1 = (const float*)d_in[3];
    const float* b1 = (const float*)d_in[4];
    const float* W2 = (const float*)d_in[5];
    const float* b2 = (const float*)d_in[6];
    float* out = (float*)d_out;
    (void)in_sizes; (void)n_in; (void)out_size;

    zero_counts_kernel<<<1, 32>>>();
    gate_kernel<<<NTOK / 8, 256>>>(x, gW, gb);

    moe_mma_kernel<DDIM, HDIM, true>
        <<<dim3(HDIM / BN, NTOK / BM, NEXP), GEMM_THREADS>>>(x, W1, b1);
    moe_mma_kernel<HDIM, DDIM, false>
        <<<dim3(DDIM / BN, NTOK / BM, NEXP), GEMM_THREADS>>>(x, W2, b2);

    combine_kernel<<<(NTOK * (DDIM / 4)) / 256, 256>>>(out);
}